// round 11
// baseline (speedup 1.0000x reference)
#include <cuda_runtime.h>
#include <cuda_fp16.h>
#include <math.h>
#include <stdint.h>

#define EPSBN 1e-5f

// layer geometry
#define HO1 130
#define WO1 258
#define HO2 132
#define WO2 260
#define TOT1 (16 * HO1 * WO1)
#define TOT2 (16 * HO2 * WO2)

// fp16 NHWC halo buffers (64 ch, 2-px halo each side).
// Halos MUST be re-zeroed every kernel_launch call (harness dirties memory
// between correctness run and timed replays — R8 post-mortem). Interiors are
// fully rewritten in-call.
__device__ __half g_xb1[(size_t)16 * 132 * 260 * 64];
__device__ __half g_xb2[(size_t)16 * 134 * 262 * 64];
__device__ __half g_y2 [(size_t)16 * 136 * 264 * 64];
// packed A blocks: [mh(2)][tap(9)][m(128)][KCI+8] fp16 (single fp16)
__device__ __half g_apk1[2 * 9 * 128 * 40];
__device__ __half g_apk2[2 * 9 * 128 * 72];
__device__ float  g_stats[4 * 64];
__device__ float  g_st[4 * 64];

// ---- helpers ----
__device__ __forceinline__ uint32_t smem_u32(const void* p) {
    uint32_t a;
    asm("{ .reg .u64 t; cvta.to.shared.u64 t, %1; cvt.u32.u64 %0, t; }" : "=r"(a) : "l"(p));
    return a;
}
#define LDSM4(r, addr) \
    asm volatile("ldmatrix.sync.aligned.m8n8.x4.shared.b16 {%0,%1,%2,%3}, [%4];" \
        : "=r"((r)[0]), "=r"((r)[1]), "=r"((r)[2]), "=r"((r)[3]) : "r"(addr))
#define LDSM2(r, addr) \
    asm volatile("ldmatrix.sync.aligned.m8n8.x2.shared.b16 {%0,%1}, [%2];" \
        : "=r"((r)[0]), "=r"((r)[1]) : "r"(addr))

__device__ __forceinline__ void hmma(float* c, const uint32_t* a, const uint32_t* b) {
    asm volatile(
        "mma.sync.aligned.m16n8k16.row.col.f32.f16.f16.f32 "
        "{%0,%1,%2,%3}, {%4,%5,%6,%7}, {%8,%9}, {%0,%1,%2,%3};"
        : "+f"(c[0]), "+f"(c[1]), "+f"(c[2]), "+f"(c[3])
        : "r"(a[0]), "r"(a[1]), "r"(a[2]), "r"(a[3]), "r"(b[0]), "r"(b[1]));
}
__device__ __forceinline__ void cpa16(uint32_t d, const void* s) {
    asm volatile("cp.async.cg.shared.global [%0], [%1], 16;" :: "r"(d), "l"(s));
}
#define CP_COMMIT() asm volatile("cp.async.commit_group;" ::: "memory")
#define CP_WAIT1()  asm volatile("cp.async.wait_group 1;" ::: "memory")

// ---- aux kernels ----
// zero ONLY the halo frame (rows 0..1, Hp-2..Hp-1; cols 0..1, Wp-2..Wp-1)
__global__ void k_zero_halo(__half* xb, int Hp, int Wp) {
    int npx = 4 * Wp + (Hp - 4) * 4;
    int tot = 16 * npx * 8;
    int idx = blockIdx.x * 256 + threadIdx.x;
    if (idx >= tot) return;
    int q = idx & 7;
    int p = (idx >> 3) % npx;
    int b = (idx >> 3) / npx;
    int row, col;
    if (p < 2 * Wp) { row = p / Wp; col = p % Wp; }
    else if (p < 4 * Wp) { int pp = p - 2 * Wp; row = Hp - 2 + pp / Wp; col = pp % Wp; }
    else {
        int s = p - 4 * Wp;
        row = 2 + (s >> 2);
        int t = s & 3;
        col = (t < 2) ? t : (Wp - 4 + t);
    }
    *((uint4*)(xb + ((size_t)(b * Hp + row) * Wp + col) * 64) + q) = make_uint4(0, 0, 0, 0);
}
__global__ void k_finalize(const float* __restrict__ sums, const float* __restrict__ gam,
                           const float* __restrict__ bet, float* __restrict__ st, float N) {
    int c = threadIdx.x;
    if (c < 64) {
        float mean = sums[c] / N;
        float var  = sums[64 + c] / N - mean * mean;
        float s    = gam[c] * rsqrtf(var + EPSBN);
        st[c]      = s;
        st[64 + c] = bet[c] - mean * s;
    }
}
// pack weights [r][64][CIN][3][3] fp32 -> [mh][tap][m=o*4+r][CIN+8] fp16.
// Block 0 also zeroes the stats accumulators (zstats != nullptr).
__global__ void k_pack(const float* __restrict__ w, __half* __restrict__ apk,
                       int CIN, int PR, float* zstats) {
    if (zstats && blockIdx.x == 0 && threadIdx.x < 256) zstats[threadIdx.x] = 0.f;
    int idx = blockIdx.x * 256 + threadIdx.x;
    const int TOTP = 2 * 9 * 128 * PR;
    if (idx >= TOTP) return;
    int kq = idx % PR;
    int m  = (idx / PR) % 128;
    int kk = (idx / (PR * 128)) % 9;
    int mh = idx / (PR * 128 * 9);
    int r = m & 3, o = mh * 32 + (m >> 2);
    int kh = kk / 3, kw = kk - kh * 3;
    float v = 0.f;
    if (kq < CIN) v = w[(((r * 64 + o) * CIN + kq) * 3 + kh) * 3 + kw];
    apk[idx] = __float2half(v);
}
// x NCHW fp32 -> xb1 NHWC fp16 halo (channels 32..63 stay zero)
__global__ __launch_bounds__(256) void k_tin(const float4* __restrict__ x4,
                                             __half* __restrict__ xb) {
    __shared__ __half ts[32][264];
    int tid = threadIdx.x;
    int b = blockIdx.x >> 7;
    int h = blockIdx.x & 127;
#pragma unroll
    for (int it = 0; it < 8; ++it) {
        int idx = tid + it * 256;
        int c = idx >> 6, w4 = idx & 63;
        float4 v = x4[((size_t)(b * 32 + c) * 128 + h) * 64 + w4];
        ts[c][w4 * 4 + 0] = __float2half(v.x);
        ts[c][w4 * 4 + 1] = __float2half(v.y);
        ts[c][w4 * 4 + 2] = __float2half(v.z);
        ts[c][w4 * 4 + 3] = __float2half(v.w);
    }
    __syncthreads();
    int w = tid;
    __half tmp[32];
#pragma unroll
    for (int c = 0; c < 32; ++c) tmp[c] = ts[c][w];
    uint4* dst = (uint4*)(xb + ((size_t)(b * 132 + h + 2) * 260 + (w + 2)) * 64);
#pragma unroll
    for (int q = 0; q < 4; ++q) dst[q] = ((uint4*)tmp)[q];
}
// BN2 + ReLU + 3x3/3 maxpool -> NCHW fp32 out
__global__ void k_pool(const __half* __restrict__ y2, const float* __restrict__ st,
                       float* __restrict__ out) {
    int idx = blockIdx.x * blockDim.x + threadIdx.x;
    const int n = 16 * 44 * 86 * 8;
    if (idx >= n) return;
    int c8 = idx & 7;
    int rem = idx >> 3;
    int ow = rem % 86; rem /= 86;
    int oh = rem % 44;
    int b = rem / 44;
    float acc[8];
#pragma unroll
    for (int j = 0; j < 8; ++j) acc[j] = 0.f;
#pragma unroll
    for (int kh = 0; kh < 3; ++kh)
#pragma unroll
        for (int kw = 0; kw < 3; ++kw) {
            const __half* p = y2 + ((size_t)(b * 136 + oh * 3 + kh + 2) * 264
                                    + (ow * 3 + kw + 2)) * 64 + c8 * 8;
            uint4 v = *(const uint4*)p;
            const __half* hv = (const __half*)&v;
#pragma unroll
            for (int j = 0; j < 8; ++j) {
                int c = c8 * 8 + j;
                float f = __half2float(hv[j]) * st[c] + st[64 + c];
                acc[j] = fmaxf(acc[j], fmaxf(f, 0.f));
            }
        }
#pragma unroll
    for (int j = 0; j < 8; ++j) {
        int c = c8 * 8 + j;
        out[((size_t)(b * 64 + c) * 44 + oh) * 86 + ow] = acc[j];
    }
}

// ---- main conv: warp-MMA implicit GEMM, warp tile m64 x n72 ----
// CTA: ONE output row h, 288 px (full row), M=128 (=32 o x 4 r, mh half).
// 8 warps: grid 2m x 4n, warp m64 x n72 (4 A frags, 9 B frags, 36 MMAs/K-step).
// 1 CTA/SM. cp.async double-buffered A.
// FUSED: apply BN(stl)+ReLU of previous layer while staging B (interior only).
template<int KCI, bool FUSED>
__global__ __launch_bounds__(256, 1)
void k_conv(const __half* __restrict__ xb, const __half* __restrict__ apk,
            const float* __restrict__ bias, const float* __restrict__ ah,
            const float* __restrict__ aw, const float* __restrict__ stl,
            __half* __restrict__ yb, float* __restrict__ stats,
            int HO, int WO, int HpIn, int WpIn, int HpOut, int WpOut)
{
    constexpr int NT     = 288;                 // px per CTA (full row)
    constexpr int STRW   = 290;                 // strip width (px + 2 halo)
    constexpr int PITCH  = 2 * KCI + 16;        // bytes per smem row
    constexpr int PRH    = KCI + 8;             // halfs per packed-A row
    constexpr int ACH    = 128 * PITCH;         // per-tap A chunk
    constexpr int KSTEPS = KCI / 16;
    constexpr int BU4    = KCI / 8;             // uint4 per B px
    constexpr int SMB  = 0;
    constexpr int SMA  = 3 * STRW * PITCH;
    constexpr int SMCW = SMA + 2 * ACH;
    constexpr int SMBI = SMCW + 4 * NT * 4;
    constexpr int SMY  = SMBI + 128;
    constexpr int SMPP = SMY + NT * 32 * 2;

    extern __shared__ char smraw[];
    char* bsm = smraw + SMB;
    float* cws = (float*)(smraw + SMCW);        // [r4][288]
    float* bias_s = (float*)(smraw + SMBI);
    __half* ysm = (__half*)(smraw + SMY);       // [288 px][32 ch]
    float2* pp = (float2*)(smraw + SMPP);
    const uint32_t SB = smem_u32(smraw);

    const int tid = threadIdx.x;
    const int lane = tid & 31;
    const int wid = tid >> 5;
    const int h  = blockIdx.y;
    const int b  = blockIdx.z >> 1;
    const int mh = blockIdx.z & 1;
    const int npx = WO;                         // single tile per row

    // prefetch A taps 0,1 (cp.async, double buffer)
    {
        constexpr int NU = ACH / 16;
#pragma unroll
        for (int t = 0; t < 2; ++t) {
            const char* src = (const char*)(apk + (size_t)((mh * 9 + t)) * 128 * PRH);
            uint32_t dst = SB + SMA + t * ACH;
            for (int i = tid; i < NU; i += 256) cpa16(dst + i * 16, src + i * 16);
            CP_COMMIT();
        }
    }

    // stage B: 3 input-row strips x 290 px (BN+ReLU fused if FUSED, interior only)
    for (int i = tid; i < 3 * STRW * BU4; i += 256) {
        int q = i % BU4;
        int p = i / BU4;
        int strip = p / STRW, c = p - strip * STRW;
        int row = h + strip;
        int col = min(c, WpIn - 1);
        uint4 v = *((const uint4*)(xb + ((size_t)(b * HpIn + row) * WpIn + col) * 64) + q);
        if (FUSED) {
            if (row >= 2 && row < HpIn - 2 && col >= 2 && col < WpIn - 2) {
                __half* hv = (__half*)&v;
#pragma unroll
                for (int j = 0; j < 8; ++j) {
                    int ch = q * 8 + j;
                    float f = __half2float(hv[j]) * stl[ch] + stl[64 + ch];
                    hv[j] = __float2half(fmaxf(f, 0.f));
                }
            }
        }
        *(uint4*)(bsm + p * PITCH + q * 16) = v;
    }
    // combining weights (softmax over rank) per pixel
    for (int i = tid; i < NT; i += 256) {
        int w = min(i, WO - 1);
        float lg[4], mx = -1e30f;
#pragma unroll
        for (int r = 0; r < 4; ++r) { lg[r] = ah[r * HO + h] + aw[r * WO + w]; mx = fmaxf(mx, lg[r]); }
        float es = 0.f;
#pragma unroll
        for (int r = 0; r < 4; ++r) { lg[r] = expf(lg[r] - mx); es += lg[r]; }
        float inv = 1.f / es;
#pragma unroll
        for (int r = 0; r < 4; ++r) cws[r * NT + i] = lg[r] * inv;
    }
    if (tid < 32) bias_s[tid] = bias[mh * 32 + tid];

    float acc[4][9][4];
#pragma unroll
    for (int mi = 0; mi < 4; ++mi)
#pragma unroll
        for (int ni = 0; ni < 9; ++ni)
#pragma unroll
            for (int c = 0; c < 4; ++c) acc[mi][ni][c] = 0.f;

    const int moff = (wid >> 2) * 64;           // 2 m-warps
    const int noff = (wid & 3) * 72;            // 4 n-warps
    const int arow = lane & 15;
    const int acol16 = (lane >> 4) * 16;
    const int brow = (lane & 7) + ((lane >> 4) << 3);
    const int bcol16 = ((lane >> 3) & 1) * 16;
    const uint32_t a_base0 = SB + SMA + (moff + arow) * PITCH + acol16;

#pragma unroll 1
    for (int kk = 0; kk < 9; ++kk) {
        CP_WAIT1();
        __syncthreads();
        const int kh = kk / 3, kw = kk - (kk / 3) * 3;
        const uint32_t a_base = a_base0 + (kk & 1) * ACH;
        const uint32_t b_base = SB + (kh * STRW + noff + kw + brow) * PITCH + bcol16;
#pragma unroll
        for (int s = 0; s < KSTEPS; ++s) {
            uint32_t af[4][4];
#pragma unroll
            for (int mi = 0; mi < 4; ++mi)
                LDSM4(af[mi], a_base + mi * (16 * PITCH) + s * 32);
            uint32_t bf[4][4];
            uint32_t b8[2];
#pragma unroll
            for (int g = 0; g < 4; ++g)
                LDSM4(bf[g], b_base + g * (16 * PITCH) + s * 32);
            LDSM2(b8, b_base + 64 * PITCH + s * 32);
#pragma unroll
            for (int mi = 0; mi < 4; ++mi) {
#pragma unroll
                for (int n8 = 0; n8 < 8; ++n8)
                    hmma(acc[mi][n8], af[mi], &bf[n8 >> 1][(n8 & 1) * 2]);
                hmma(acc[mi][8], af[mi], b8);
            }
        }
        __syncthreads();
        if (kk + 2 < 9) {
            constexpr int NU = ACH / 16;
            const char* src = (const char*)(apk + (size_t)((mh * 9 + kk + 2)) * 128 * PRH);
            uint32_t dst = SB + SMA + (kk & 1) * ACH;
            for (int i = tid; i < NU; i += 256) cpa16(dst + i * 16, src + i * 16);
            CP_COMMIT();
        }
    }

    // ---- epilogue: rank combine (shfl over r), bias, fp16 to ysm ----
    const int r4 = (lane >> 2) & 3;
    const bool lead = (r4 == 0);
#pragma unroll
    for (int mi = 0; mi < 4; ++mi)
#pragma unroll
        for (int ni = 0; ni < 9; ++ni) {
            int px0 = noff + 8 * ni + 2 * (lane & 3);
            float v0 = acc[mi][ni][0] * cws[r4 * NT + px0];
            float v1 = acc[mi][ni][1] * cws[r4 * NT + px0 + 1];
            float v2 = acc[mi][ni][2] * cws[r4 * NT + px0];
            float v3 = acc[mi][ni][3] * cws[r4 * NT + px0 + 1];
            v0 += __shfl_xor_sync(~0u, v0, 4); v0 += __shfl_xor_sync(~0u, v0, 8);
            v1 += __shfl_xor_sync(~0u, v1, 4); v1 += __shfl_xor_sync(~0u, v1, 8);
            v2 += __shfl_xor_sync(~0u, v2, 4); v2 += __shfl_xor_sync(~0u, v2, 8);
            v3 += __shfl_xor_sync(~0u, v3, 4); v3 += __shfl_xor_sync(~0u, v3, 8);
            if (lead) {
                int o0 = (moff + 16 * mi + (lane >> 2)) >> 2;
                int o2 = o0 + 2;
                __half* yr = ysm + px0 * 32;
                yr[o0]      = __float2half(v0 + bias_s[o0]);
                yr[32 + o0] = __float2half(v1 + bias_s[o0]);
                yr[o2]      = __float2half(v2 + bias_s[o2]);
                yr[32 + o2] = __float2half(v3 + bias_s[o2]);
            }
        }
    __syncthreads();

    // BN stats (valid px only)
    {
        int ol = tid & 31, pb = tid >> 5;
        float s0 = 0.f, s1 = 0.f;
#pragma unroll
        for (int jj = 0; jj < 36; ++jj) {
            int j = pb * 36 + jj;
            if (j < npx) {
                float v = __half2float(ysm[j * 32 + ol]);
                s0 += v; s1 += v * v;
            }
        }
        pp[pb * 32 + ol] = make_float2(s0, s1);
    }
    __syncthreads();
    if (tid < 32) {
        float a0 = 0.f, a1 = 0.f;
#pragma unroll
        for (int pb2 = 0; pb2 < 8; ++pb2) {
            float2 u = pp[pb2 * 32 + tid];
            a0 += u.x; a1 += u.y;
        }
        atomicAdd(&stats[mh * 32 + tid], a0);
        atomicAdd(&stats[64 + mh * 32 + tid], a1);
    }
    // store NHWC fp16 (this CTA's 32-ch half), halo offset +2
    for (int i = tid; i < npx * 4; i += 256) {
        int p = i >> 2, q = i & 3;
        *(uint4*)(yb + ((size_t)(b * HpOut + h + 2) * WpOut + (p + 2)) * 64
                  + mh * 32 + q * 8) = *(const uint4*)(ysm + p * 32 + q * 8);
    }
}

extern "C" void kernel_launch(void* const* d_in, const int* in_sizes, int n_in,
                              void* d_out, int out_size) {
    const float* x   = (const float*)d_in[0];
    const float* w1  = (const float*)d_in[1];
    const float* b1  = (const float*)d_in[2];
    const float* a1h = (const float*)d_in[3];
    const float* a1w = (const float*)d_in[4];
    const float* g1  = (const float*)d_in[5];
    const float* be1 = (const float*)d_in[6];
    const float* w2  = (const float*)d_in[7];
    const float* b2  = (const float*)d_in[8];
    const float* a2h = (const float*)d_in[9];
    const float* a2w = (const float*)d_in[10];
    const float* g2  = (const float*)d_in[11];
    const float* be2 = (const float*)d_in[12];

    __half *xb1, *xb2, *y2, *ap1, *ap2;
    float *stats, *st;
    cudaGetSymbolAddress((void**)&xb1, g_xb1);
    cudaGetSymbolAddress((void**)&xb2, g_xb2);
    cudaGetSymbolAddress((void**)&y2, g_y2);
    cudaGetSymbolAddress((void**)&ap1, g_apk1);
    cudaGetSymbolAddress((void**)&ap2, g_apk2);
    cudaGetSymbolAddress((void**)&stats, g_stats);
    cudaGetSymbolAddress((void**)&st, g_st);

    // smem: 3*290*PITCH + 2*128*PITCH + 4*288*4 + 128 + 288*64 + 2048
    const int SM1 = 3 * 290 * 80 + 2 * 128 * 80 + 4608 + 128 + 18432 + 2048;    // 115,296
    const int SM2 = 3 * 290 * 144 + 2 * 128 * 144 + 4608 + 128 + 18432 + 2048;  // 187,360
    cudaFuncSetAttribute(k_conv<32, false>, cudaFuncAttributeMaxDynamicSharedMemorySize, SM1);
    cudaFuncSetAttribute(k_conv<64, true>,  cudaFuncAttributeMaxDynamicSharedMemorySize, SM2);

    // Launch order chosen so k_conv1 is the 6th launch (ncu -s 5 -c 1 profiles it).
    k_zero_halo<<<(16 * (4 * 260 + 128 * 4) * 8 + 255) / 256, 256>>>(xb1, 132, 260);   // 1
    k_zero_halo<<<(16 * (4 * 262 + 130 * 4) * 8 + 255) / 256, 256>>>(xb2, 134, 262);   // 2
    k_pack<<<(2 * 9 * 128 * 40 + 255) / 256, 256>>>(w1, ap1, 32, 40, stats);           // 3 (+stats zero)
    k_pack<<<(2 * 9 * 128 * 72 + 255) / 256, 256>>>(w2, ap2, 64, 72, nullptr);         // 4
    k_tin<<<16 * 128, 256>>>((const float4*)x, xb1);                                   // 5

    k_conv<32, false><<<dim3(1, HO1, 32), 256, SM1>>>(xb1, ap1, b1, a1h, a1w, nullptr, // 6
                                                      xb2, stats, HO1, WO1, 132, 260, 134, 262);
    k_finalize<<<1, 64>>>(stats, g1, be1, st, (float)TOT1);                            // 7

    k_conv<64, true><<<dim3(1, HO2, 32), 256, SM2>>>(xb2, ap2, b2, a2h, a2w, st,       // 8
                                                     y2, stats + 128, HO2, WO2, 134, 262, 136, 264);
    k_finalize<<<1, 64>>>(stats + 128, g2, be2, st + 128, (float)TOT2);                // 9

    k_pool<<<(16 * 44 * 86 * 8 + 255) / 256, 256>>>(y2, st + 128, (float*)d_out);      // 10
}

// round 13
// speedup vs baseline: 1.0906x; 1.0906x over previous
#include <cuda_runtime.h>
#include <cuda_fp16.h>
#include <math.h>
#include <stdint.h>

#define EPSBN 1e-5f

// layer geometry
#define HO1 130
#define WO1 258
#define HO2 132
#define WO2 260
#define TOT1 (16 * HO1 * WO1)
#define TOT2 (16 * HO2 * WO2)

// fp16 NHWC halo buffers (64 ch, 2-px halo each side).
// Halos MUST be re-zeroed every kernel_launch call (harness dirties memory
// between correctness run and timed replays — R8 post-mortem).
__device__ __half g_xb1[(size_t)16 * 132 * 260 * 64];
__device__ __half g_xb2[(size_t)16 * 134 * 262 * 64];
__device__ __half g_y2 [(size_t)16 * 136 * 264 * 64];
// packed A blocks: [mh(2)][tap(9)][m(128)][KCI+8] fp16
__device__ __half g_apk1[2 * 9 * 128 * 40];
__device__ __half g_apk2[2 * 9 * 128 * 72];
__device__ float  g_stats[4 * 64];
__device__ float  g_st[4 * 64];

// ---- helpers ----
__device__ __forceinline__ uint32_t smem_u32(const void* p) {
    uint32_t a;
    asm("{ .reg .u64 t; cvta.to.shared.u64 t, %1; cvt.u32.u64 %0, t; }" : "=r"(a) : "l"(p));
    return a;
}
#define LDSM4(r, addr) \
    asm volatile("ldmatrix.sync.aligned.m8n8.x4.shared.b16 {%0,%1,%2,%3}, [%4];" \
        : "=r"((r)[0]), "=r"((r)[1]), "=r"((r)[2]), "=r"((r)[3]) : "r"(addr))

__device__ __forceinline__ void hmma(float* c, const uint32_t* a, const uint32_t* b) {
    asm volatile(
        "mma.sync.aligned.m16n8k16.row.col.f32.f16.f16.f32 "
        "{%0,%1,%2,%3}, {%4,%5,%6,%7}, {%8,%9}, {%0,%1,%2,%3};"
        : "+f"(c[0]), "+f"(c[1]), "+f"(c[2]), "+f"(c[3])
        : "r"(a[0]), "r"(a[1]), "r"(a[2]), "r"(a[3]), "r"(b[0]), "r"(b[1]));
}
__device__ __forceinline__ void cpa16(uint32_t d, const void* s) {
    asm volatile("cp.async.cg.shared.global [%0], [%1], 16;" :: "r"(d), "l"(s));
}
#define CP_COMMIT() asm volatile("cp.async.commit_group;" ::: "memory")
#define CP_WAIT1()  asm volatile("cp.async.wait_group 1;" ::: "memory")

// ---- aux kernels ----
// zero ONLY the halo frame (rows 0..1, Hp-2..Hp-1; cols 0..1, Wp-2..Wp-1)
__global__ void k_zero_halo(__half* xb, int Hp, int Wp) {
    int npx = 4 * Wp + (Hp - 4) * 4;
    int tot = 16 * npx * 8;
    int idx = blockIdx.x * 256 + threadIdx.x;
    if (idx >= tot) return;
    int q = idx & 7;
    int p = (idx >> 3) % npx;
    int b = (idx >> 3) / npx;
    int row, col;
    if (p < 2 * Wp) { row = p / Wp; col = p % Wp; }
    else if (p < 4 * Wp) { int pp = p - 2 * Wp; row = Hp - 2 + pp / Wp; col = pp % Wp; }
    else {
        int s = p - 4 * Wp;
        row = 2 + (s >> 2);
        int t = s & 3;
        col = (t < 2) ? t : (Wp - 4 + t);
    }
    *((uint4*)(xb + ((size_t)(b * Hp + row) * Wp + col) * 64) + q) = make_uint4(0, 0, 0, 0);
}
__global__ void k_finalize(const float* __restrict__ sums, const float* __restrict__ gam,
                           const float* __restrict__ bet, float* __restrict__ st, float N) {
    int c = threadIdx.x;
    if (c < 64) {
        float mean = sums[c] / N;
        float var  = sums[64 + c] / N - mean * mean;
        float s    = gam[c] * rsqrtf(var + EPSBN);
        st[c]      = s;
        st[64 + c] = bet[c] - mean * s;
    }
}
// pack weights [r][64][CIN][3][3] fp32 -> [mh][tap][m=o*4+r][CIN+8] fp16.
// Block 0 also zeroes the stats accumulators (zstats != nullptr).
__global__ void k_pack(const float* __restrict__ w, __half* __restrict__ apk,
                       int CIN, int PR, float* zstats) {
    if (zstats && blockIdx.x == 0 && threadIdx.x < 256) zstats[threadIdx.x] = 0.f;
    int idx = blockIdx.x * 256 + threadIdx.x;
    const int TOTP = 2 * 9 * 128 * PR;
    if (idx >= TOTP) return;
    int kq = idx % PR;
    int m  = (idx / PR) % 128;
    int kk = (idx / (PR * 128)) % 9;
    int mh = idx / (PR * 128 * 9);
    int r = m & 3, o = mh * 32 + (m >> 2);
    int kh = kk / 3, kw = kk - kh * 3;
    float v = 0.f;
    if (kq < CIN) v = w[(((r * 64 + o) * CIN + kq) * 3 + kh) * 3 + kw];
    apk[idx] = __float2half(v);
}
// x NCHW fp32 -> xb1 NHWC fp16 halo (channels 32..63 stay zero)
__global__ __launch_bounds__(256) void k_tin(const float4* __restrict__ x4,
                                             __half* __restrict__ xb) {
    __shared__ __half ts[32][264];
    int tid = threadIdx.x;
    int b = blockIdx.x >> 7;
    int h = blockIdx.x & 127;
#pragma unroll
    for (int it = 0; it < 8; ++it) {
        int idx = tid + it * 256;
        int c = idx >> 6, w4 = idx & 63;
        float4 v = x4[((size_t)(b * 32 + c) * 128 + h) * 64 + w4];
        ts[c][w4 * 4 + 0] = __float2half(v.x);
        ts[c][w4 * 4 + 1] = __float2half(v.y);
        ts[c][w4 * 4 + 2] = __float2half(v.z);
        ts[c][w4 * 4 + 3] = __float2half(v.w);
    }
    __syncthreads();
    int w = tid;
    __half tmp[32];
#pragma unroll
    for (int c = 0; c < 32; ++c) tmp[c] = ts[c][w];
    uint4* dst = (uint4*)(xb + ((size_t)(b * 132 + h + 2) * 260 + (w + 2)) * 64);
#pragma unroll
    for (int q = 0; q < 4; ++q) dst[q] = ((uint4*)tmp)[q];
}
// BN2 + ReLU + 3x3/3 maxpool -> NCHW fp32 out
__global__ void k_pool(const __half* __restrict__ y2, const float* __restrict__ st,
                       float* __restrict__ out) {
    int idx = blockIdx.x * blockDim.x + threadIdx.x;
    const int n = 16 * 44 * 86 * 8;
    if (idx >= n) return;
    int c8 = idx & 7;
    int rem = idx >> 3;
    int ow = rem % 86; rem /= 86;
    int oh = rem % 44;
    int b = rem / 44;
    float acc[8];
#pragma unroll
    for (int j = 0; j < 8; ++j) acc[j] = 0.f;
#pragma unroll
    for (int kh = 0; kh < 3; ++kh)
#pragma unroll
        for (int kw = 0; kw < 3; ++kw) {
            const __half* p = y2 + ((size_t)(b * 136 + oh * 3 + kh + 2) * 264
                                    + (ow * 3 + kw + 2)) * 64 + c8 * 8;
            uint4 v = *(const uint4*)p;
            const __half* hv = (const __half*)&v;
#pragma unroll
            for (int j = 0; j < 8; ++j) {
                int c = c8 * 8 + j;
                float f = __half2float(hv[j]) * st[c] + st[64 + c];
                acc[j] = fmaxf(acc[j], fmaxf(f, 0.f));
            }
        }
#pragma unroll
    for (int j = 0; j < 8; ++j) {
        int c = c8 * 8 + j;
        out[((size_t)(b * 64 + c) * 44 + oh) * 86 + ow] = acc[j];
    }
}

// ---- main conv: warp-MMA implicit GEMM, 384 threads, warp tile m64 x n48 ----
// CTA: ONE output row h, 288 px, M=128 (=32 o x 4 r, mh half).
// 12 warps: grid 2m x 6n; per s-iter: 4 A-LDSM4 + 3 B-LDSM4 -> 24 MMAs
// (wf/MMA = 1.17 vs R9's 1.44). 170-reg cap, 1 CTA/SM, 12 warps (3/SMSP).
// cp.async double-buffered A.
// FUSED: apply BN(stl)+ReLU of previous layer while staging B (interior only).
template<int KCI, bool FUSED>
__global__ __launch_bounds__(384, 1)
void k_conv(const __half* __restrict__ xb, const __half* __restrict__ apk,
            const float* __restrict__ bias, const float* __restrict__ ah,
            const float* __restrict__ aw, const float* __restrict__ stl,
            __half* __restrict__ yb, float* __restrict__ stats,
            int HO, int WO, int HpIn, int WpIn, int HpOut, int WpOut)
{
    constexpr int NTH    = 384;
    constexpr int NT     = 288;                 // px per CTA (full row)
    constexpr int STRW   = 290;                 // strip width (px + 2 halo)
    constexpr int PITCH  = 2 * KCI + 16;        // bytes per smem row
    constexpr int PRH    = KCI + 8;             // halfs per packed-A row
    constexpr int ACH    = 128 * PITCH;         // per-tap A chunk
    constexpr int KSTEPS = KCI / 16;
    constexpr int BU4    = KCI / 8;             // uint4 per B px
    constexpr int SMB  = 0;
    constexpr int SMA  = 3 * STRW * PITCH;
    constexpr int SMCW = SMA + 2 * ACH;
    constexpr int SMBI = SMCW + 4 * NT * 4;
    constexpr int SMY  = SMBI + 128;
    constexpr int SMPP = SMY + NT * 32 * 2;     // pp: 12 warps * 32 ch * float2 = 3072 B

    extern __shared__ char smraw[];
    char* bsm = smraw + SMB;
    float* cws = (float*)(smraw + SMCW);        // [r4][288]
    float* bias_s = (float*)(smraw + SMBI);
    __half* ysm = (__half*)(smraw + SMY);       // [288 px][32 ch]
    float2* pp = (float2*)(smraw + SMPP);
    const uint32_t SB = smem_u32(smraw);

    const int tid = threadIdx.x;
    const int lane = tid & 31;
    const int wid = tid >> 5;                   // 0..11
    const int h  = blockIdx.y;
    const int b  = blockIdx.z >> 1;
    const int mh = blockIdx.z & 1;
    const int npx = WO;

    // prefetch A taps 0,1 (cp.async, double buffer)
    {
        constexpr int NU = ACH / 16;
#pragma unroll
        for (int t = 0; t < 2; ++t) {
            const char* src = (const char*)(apk + (size_t)((mh * 9 + t)) * 128 * PRH);
            uint32_t dst = SB + SMA + t * ACH;
            for (int i = tid; i < NU; i += NTH) cpa16(dst + i * 16, src + i * 16);
            CP_COMMIT();
        }
    }

    // stage B: 3 input-row strips x 290 px (BN+ReLU fused if FUSED, interior only)
    for (int i = tid; i < 3 * STRW * BU4; i += NTH) {
        int q = i % BU4;
        int p = i / BU4;
        int strip = p / STRW, c = p - strip * STRW;
        int row = h + strip;
        int col = min(c, WpIn - 1);
        uint4 v = *((const uint4*)(xb + ((size_t)(b * HpIn + row) * WpIn + col) * 64) + q);
        if (FUSED) {
            if (row >= 2 && row < HpIn - 2 && col >= 2 && col < WpIn - 2) {
                __half* hv = (__half*)&v;
#pragma unroll
                for (int j = 0; j < 8; ++j) {
                    int ch = q * 8 + j;
                    float f = __half2float(hv[j]) * stl[ch] + stl[64 + ch];
                    hv[j] = __float2half(fmaxf(f, 0.f));
                }
            }
        }
        *(uint4*)(bsm + p * PITCH + q * 16) = v;
    }
    // combining weights (softmax over rank) per pixel
    for (int i = tid; i < NT; i += NTH) {
        int w = min(i, WO - 1);
        float lg[4], mx = -1e30f;
#pragma unroll
        for (int r = 0; r < 4; ++r) { lg[r] = ah[r * HO + h] + aw[r * WO + w]; mx = fmaxf(mx, lg[r]); }
        float es = 0.f;
#pragma unroll
        for (int r = 0; r < 4; ++r) { lg[r] = expf(lg[r] - mx); es += lg[r]; }
        float inv = 1.f / es;
#pragma unroll
        for (int r = 0; r < 4; ++r) cws[r * NT + i] = lg[r] * inv;
    }
    if (tid < 32) bias_s[tid] = bias[mh * 32 + tid];

    float acc[4][6][4];
#pragma unroll
    for (int mi = 0; mi < 4; ++mi)
#pragma unroll
        for (int ni = 0; ni < 6; ++ni)
#pragma unroll
            for (int c = 0; c < 4; ++c) acc[mi][ni][c] = 0.f;

    const int moff = (wid / 6) * 64;            // 2 m-warps
    const int noff = (wid % 6) * 48;            // 6 n-warps
    const int arow = lane & 15;
    const int acol16 = (lane >> 4) * 16;
    const int brow = (lane & 7) + ((lane >> 4) << 3);
    const int bcol16 = ((lane >> 3) & 1) * 16;
    const uint32_t a_base0 = SB + SMA + (moff + arow) * PITCH + acol16;

#pragma unroll 1
    for (int kk = 0; kk < 9; ++kk) {
        CP_WAIT1();
        __syncthreads();
        const int kh = kk / 3, kw = kk - (kk / 3) * 3;
        const uint32_t a_base = a_base0 + (kk & 1) * ACH;
        const uint32_t b_base = SB + (kh * STRW + noff + kw + brow) * PITCH + bcol16;
#pragma unroll
        for (int s = 0; s < KSTEPS; ++s) {
            uint32_t af[4][4];
#pragma unroll
            for (int mi = 0; mi < 4; ++mi)
                LDSM4(af[mi], a_base + mi * (16 * PITCH) + s * 32);
            uint32_t bf[3][4];
#pragma unroll
            for (int g = 0; g < 3; ++g)
                LDSM4(bf[g], b_base + g * (16 * PITCH) + s * 32);
#pragma unroll
            for (int mi = 0; mi < 4; ++mi)
#pragma unroll
                for (int n8 = 0; n8 < 6; ++n8)
                    hmma(acc[mi][n8], af[mi], &bf[n8 >> 1][(n8 & 1) * 2]);
        }
        __syncthreads();
        if (kk + 2 < 9) {
            constexpr int NU = ACH / 16;
            const char* src = (const char*)(apk + (size_t)((mh * 9 + kk + 2)) * 128 * PRH);
            uint32_t dst = SB + SMA + (kk & 1) * ACH;
            for (int i = tid; i < NU; i += NTH) cpa16(dst + i * 16, src + i * 16);
            CP_COMMIT();
        }
    }

    // ---- epilogue: rank combine (shfl over r), bias, fp16 to ysm ----
    const int r4 = (lane >> 2) & 3;
    const bool lead = (r4 == 0);
#pragma unroll
    for (int mi = 0; mi < 4; ++mi)
#pragma unroll
        for (int ni = 0; ni < 6; ++ni) {
            int px0 = noff + 8 * ni + 2 * (lane & 3);
            float v0 = acc[mi][ni][0] * cws[r4 * NT + px0];
            float v1 = acc[mi][ni][1] * cws[r4 * NT + px0 + 1];
            float v2 = acc[mi][ni][2] * cws[r4 * NT + px0];
            float v3 = acc[mi][ni][3] * cws[r4 * NT + px0 + 1];
            v0 += __shfl_xor_sync(~0u, v0, 4); v0 += __shfl_xor_sync(~0u, v0, 8);
            v1 += __shfl_xor_sync(~0u, v1, 4); v1 += __shfl_xor_sync(~0u, v1, 8);
            v2 += __shfl_xor_sync(~0u, v2, 4); v2 += __shfl_xor_sync(~0u, v2, 8);
            v3 += __shfl_xor_sync(~0u, v3, 4); v3 += __shfl_xor_sync(~0u, v3, 8);
            if (lead) {
                int o0 = (moff + 16 * mi + (lane >> 2)) >> 2;
                int o2 = o0 + 2;
                __half* yr = ysm + px0 * 32;
                yr[o0]      = __float2half(v0 + bias_s[o0]);
                yr[32 + o0] = __float2half(v1 + bias_s[o0]);
                yr[o2]      = __float2half(v2 + bias_s[o2]);
                yr[32 + o2] = __float2half(v3 + bias_s[o2]);
            }
        }
    __syncthreads();

    // BN stats (valid px only): 12 warp-blocks of 24 px
    {
        int ol = tid & 31, pb = tid >> 5;
        float s0 = 0.f, s1 = 0.f;
#pragma unroll
        for (int jj = 0; jj < 24; ++jj) {
            int j = pb * 24 + jj;
            if (j < npx) {
                float v = __half2float(ysm[j * 32 + ol]);
                s0 += v; s1 += v * v;
            }
        }
        pp[pb * 32 + ol] = make_float2(s0, s1);
    }
    __syncthreads();
    if (tid < 32) {
        float a0 = 0.f, a1 = 0.f;
#pragma unroll
        for (int pb2 = 0; pb2 < 12; ++pb2) {
            float2 u = pp[pb2 * 32 + tid];
            a0 += u.x; a1 += u.y;
        }
        atomicAdd(&stats[mh * 32 + tid], a0);
        atomicAdd(&stats[64 + mh * 32 + tid], a1);
    }
    // store NHWC fp16 (this CTA's 32-ch half), halo offset +2
    for (int i = tid; i < npx * 4; i += NTH) {
        int p = i >> 2, q = i & 3;
        *(uint4*)(yb + ((size_t)(b * HpOut + h + 2) * WpOut + (p + 2)) * 64
                  + mh * 32 + q * 8) = *(const uint4*)(ysm + p * 32 + q * 8);
    }
}

extern "C" void kernel_launch(void* const* d_in, const int* in_sizes, int n_in,
                              void* d_out, int out_size) {
    const float* x   = (const float*)d_in[0];
    const float* w1  = (const float*)d_in[1];
    const float* b1  = (const float*)d_in[2];
    const float* a1h = (const float*)d_in[3];
    const float* a1w = (const float*)d_in[4];
    const float* g1  = (const float*)d_in[5];
    const float* be1 = (const float*)d_in[6];
    const float* w2  = (const float*)d_in[7];
    const float* b2  = (const float*)d_in[8];
    const float* a2h = (const float*)d_in[9];
    const float* a2w = (const float*)d_in[10];
    const float* g2  = (const float*)d_in[11];
    const float* be2 = (const float*)d_in[12];

    __half *xb1, *xb2, *y2, *ap1, *ap2;
    float *stats, *st;
    cudaGetSymbolAddress((void**)&xb1, g_xb1);
    cudaGetSymbolAddress((void**)&xb2, g_xb2);
    cudaGetSymbolAddress((void**)&y2, g_y2);
    cudaGetSymbolAddress((void**)&ap1, g_apk1);
    cudaGetSymbolAddress((void**)&ap2, g_apk2);
    cudaGetSymbolAddress((void**)&stats, g_stats);
    cudaGetSymbolAddress((void**)&st, g_st);

    // smem: B + 2*A + cws + bias + ysm + pp(12 warps * 32 * 8B = 3072)
    const int SM1 = 3 * 290 * 80 + 2 * 128 * 80 + 4608 + 128 + 18432 + 3072;    // 116,320
    const int SM2 = 3 * 290 * 144 + 2 * 128 * 144 + 4608 + 128 + 18432 + 3072;  // 188,384
    cudaFuncSetAttribute(k_conv<32, false>, cudaFuncAttributeMaxDynamicSharedMemorySize, SM1);
    cudaFuncSetAttribute(k_conv<64, true>,  cudaFuncAttributeMaxDynamicSharedMemorySize, SM2);

    // Launch order: conv1 is launch #4 (ncu empirically profiles the 4th launch).
    k_tin<<<16 * 128, 256>>>((const float4*)x, xb1);                                   // 1
    k_zero_halo<<<(16 * (4 * 260 + 128 * 4) * 8 + 255) / 256, 256>>>(xb1, 132, 260);   // 2
    k_pack<<<(2 * 9 * 128 * 40 + 255) / 256, 256>>>(w1, ap1, 32, 40, stats);           // 3 (+stats zero)
    k_conv<32, false><<<dim3(1, HO1, 32), 384, SM1>>>(xb1, ap1, b1, a1h, a1w, nullptr, // 4
                                                      xb2, stats, HO1, WO1, 132, 260, 134, 262);
    k_pack<<<(2 * 9 * 128 * 72 + 255) / 256, 256>>>(w2, ap2, 64, 72, nullptr);         // 5
    k_zero_halo<<<(16 * (4 * 262 + 130 * 4) * 8 + 255) / 256, 256>>>(xb2, 134, 262);   // 6
    k_finalize<<<1, 64>>>(stats, g1, be1, st, (float)TOT1);                            // 7
    k_conv<64, true><<<dim3(1, HO2, 32), 384, SM2>>>(xb2, ap2, b2, a2h, a2w, st,       // 8
                                                     y2, stats + 128, HO2, WO2, 134, 262, 136, 264);
    k_finalize<<<1, 64>>>(stats + 128, g2, be2, st + 128, (float)TOT2);                // 9
    k_pool<<<(16 * 44 * 86 * 8 + 255) / 256, 256>>>(y2, st + 128, (float*)d_out);      // 10
}

// round 14
// speedup vs baseline: 1.3730x; 1.2589x over previous
#include <cuda_runtime.h>
#include <cuda_fp16.h>
#include <math.h>
#include <stdint.h>

#define EPSBN 1e-5f

// layer geometry
#define HO1 130
#define WO1 258
#define HO2 132
#define WO2 260
#define TOT1 (16 * HO1 * WO1)
#define TOT2 (16 * HO2 * WO2)

// fp16 NHWC halo buffers (64 ch, 2-px halo each side).
// Halos MUST be re-zeroed every kernel_launch call (harness dirties memory
// between correctness run and timed replays — R8 post-mortem).
__device__ __half g_xb1[(size_t)16 * 132 * 260 * 64];
__device__ __half g_xb2[(size_t)16 * 134 * 262 * 64];
__device__ __half g_y2 [(size_t)16 * 136 * 264 * 64];
// packed A blocks: [mh(2)][tap(9)][m(128)][KCI+8] fp16
__device__ __half g_apk1[2 * 9 * 128 * 40];
__device__ __half g_apk2[2 * 9 * 128 * 72];
__device__ float  g_stats[4 * 64];
__device__ float  g_st[4 * 64];

// ---- helpers ----
__device__ __forceinline__ uint32_t smem_u32(const void* p) {
    uint32_t a;
    asm("{ .reg .u64 t; cvta.to.shared.u64 t, %1; cvt.u32.u64 %0, t; }" : "=r"(a) : "l"(p));
    return a;
}
#define LDSM4(r, addr) \
    asm volatile("ldmatrix.sync.aligned.m8n8.x4.shared.b16 {%0,%1,%2,%3}, [%4];" \
        : "=r"((r)[0]), "=r"((r)[1]), "=r"((r)[2]), "=r"((r)[3]) : "r"(addr))
#define LDSM2(r, addr) \
    asm volatile("ldmatrix.sync.aligned.m8n8.x2.shared.b16 {%0,%1}, [%2];" \
        : "=r"((r)[0]), "=r"((r)[1]) : "r"(addr))

__device__ __forceinline__ void hmma(float* c, const uint32_t* a, const uint32_t* b) {
    asm volatile(
        "mma.sync.aligned.m16n8k16.row.col.f32.f16.f16.f32 "
        "{%0,%1,%2,%3}, {%4,%5,%6,%7}, {%8,%9}, {%0,%1,%2,%3};"
        : "+f"(c[0]), "+f"(c[1]), "+f"(c[2]), "+f"(c[3])
        : "r"(a[0]), "r"(a[1]), "r"(a[2]), "r"(a[3]), "r"(b[0]), "r"(b[1]));
}
__device__ __forceinline__ void cpa16(uint32_t d, const void* s) {
    asm volatile("cp.async.cg.shared.global [%0], [%1], 16;" :: "r"(d), "l"(s));
}
#define CP_COMMIT() asm volatile("cp.async.commit_group;" ::: "memory")
#define CP_WAIT1()  asm volatile("cp.async.wait_group 1;" ::: "memory")
#define CP_WAIT0()  asm volatile("cp.async.wait_group 0;" ::: "memory")

// ---- aux kernels ----
// zero ONLY the halo frame (rows 0..1, Hp-2..Hp-1; cols 0..1, Wp-2..Wp-1)
__global__ void k_zero_halo(__half* xb, int Hp, int Wp) {
    int npx = 4 * Wp + (Hp - 4) * 4;
    int tot = 16 * npx * 8;
    int idx = blockIdx.x * 256 + threadIdx.x;
    if (idx >= tot) return;
    int q = idx & 7;
    int p = (idx >> 3) % npx;
    int b = (idx >> 3) / npx;
    int row, col;
    if (p < 2 * Wp) { row = p / Wp; col = p % Wp; }
    else if (p < 4 * Wp) { int pp = p - 2 * Wp; row = Hp - 2 + pp / Wp; col = pp % Wp; }
    else {
        int s = p - 4 * Wp;
        row = 2 + (s >> 2);
        int t = s & 3;
        col = (t < 2) ? t : (Wp - 4 + t);
    }
    *((uint4*)(xb + ((size_t)(b * Hp + row) * Wp + col) * 64) + q) = make_uint4(0, 0, 0, 0);
}
__global__ void k_finalize(const float* __restrict__ sums, const float* __restrict__ gam,
                           const float* __restrict__ bet, float* __restrict__ st, float N) {
    int c = threadIdx.x;
    if (c < 64) {
        float mean = sums[c] / N;
        float var  = sums[64 + c] / N - mean * mean;
        float s    = gam[c] * rsqrtf(var + EPSBN);
        st[c]      = s;
        st[64 + c] = bet[c] - mean * s;
    }
}
// pack weights [r][64][CIN][3][3] fp32 -> [mh][tap][m=o*4+r][CIN+8] fp16.
// Block 0 also zeroes the stats accumulators (zstats != nullptr).
__global__ void k_pack(const float* __restrict__ w, __half* __restrict__ apk,
                       int CIN, int PR, float* zstats) {
    if (zstats && blockIdx.x == 0 && threadIdx.x < 256) zstats[threadIdx.x] = 0.f;
    int idx = blockIdx.x * 256 + threadIdx.x;
    const int TOTP = 2 * 9 * 128 * PR;
    if (idx >= TOTP) return;
    int kq = idx % PR;
    int m  = (idx / PR) % 128;
    int kk = (idx / (PR * 128)) % 9;
    int mh = idx / (PR * 128 * 9);
    int r = m & 3, o = mh * 32 + (m >> 2);
    int kh = kk / 3, kw = kk - kh * 3;
    float v = 0.f;
    if (kq < CIN) v = w[(((r * 64 + o) * CIN + kq) * 3 + kh) * 3 + kw];
    apk[idx] = __float2half(v);
}
// x NCHW fp32 -> xb1 NHWC fp16 halo (channels 32..63 stay zero)
__global__ __launch_bounds__(256) void k_tin(const float4* __restrict__ x4,
                                             __half* __restrict__ xb) {
    __shared__ __half ts[32][264];
    int tid = threadIdx.x;
    int b = blockIdx.x >> 7;
    int h = blockIdx.x & 127;
#pragma unroll
    for (int it = 0; it < 8; ++it) {
        int idx = tid + it * 256;
        int c = idx >> 6, w4 = idx & 63;
        float4 v = x4[((size_t)(b * 32 + c) * 128 + h) * 64 + w4];
        ts[c][w4 * 4 + 0] = __float2half(v.x);
        ts[c][w4 * 4 + 1] = __float2half(v.y);
        ts[c][w4 * 4 + 2] = __float2half(v.z);
        ts[c][w4 * 4 + 3] = __float2half(v.w);
    }
    __syncthreads();
    int w = tid;
    __half tmp[32];
#pragma unroll
    for (int c = 0; c < 32; ++c) tmp[c] = ts[c][w];
    uint4* dst = (uint4*)(xb + ((size_t)(b * 132 + h + 2) * 260 + (w + 2)) * 64);
#pragma unroll
    for (int q = 0; q < 4; ++q) dst[q] = ((uint4*)tmp)[q];
}
// BN2 + ReLU + 3x3/3 maxpool -> NCHW fp32 out
__global__ void k_pool(const __half* __restrict__ y2, const float* __restrict__ st,
                       float* __restrict__ out) {
    int idx = blockIdx.x * blockDim.x + threadIdx.x;
    const int n = 16 * 44 * 86 * 8;
    if (idx >= n) return;
    int c8 = idx & 7;
    int rem = idx >> 3;
    int ow = rem % 86; rem /= 86;
    int oh = rem % 44;
    int b = rem / 44;
    float acc[8];
#pragma unroll
    for (int j = 0; j < 8; ++j) acc[j] = 0.f;
#pragma unroll
    for (int kh = 0; kh < 3; ++kh)
#pragma unroll
        for (int kw = 0; kw < 3; ++kw) {
            const __half* p = y2 + ((size_t)(b * 136 + oh * 3 + kh + 2) * 264
                                    + (ow * 3 + kw + 2)) * 64 + c8 * 8;
            uint4 v = *(const uint4*)p;
            const __half* hv = (const __half*)&v;
#pragma unroll
            for (int j = 0; j < 8; ++j) {
                int c = c8 * 8 + j;
                float f = __half2float(hv[j]) * st[c] + st[64 + c];
                acc[j] = fmaxf(acc[j], fmaxf(f, 0.f));
            }
        }
#pragma unroll
    for (int j = 0; j < 8; ++j) {
        int c = c8 * 8 + j;
        out[((size_t)(b * 64 + c) * 44 + oh) * 86 + ow] = acc[j];
    }
}

// ---- main conv: warp-MMA implicit GEMM (R9 geometry + grouped A staging) ----
// CTA: one output row h, 144 px (2 tiles/row), M=128 (=32 o x 4 r, mh half).
// 8 warps: grid 4m x 2n, warp tile m32 x n72. 2 CTAs/SM (128 regs, <=113.6KB smem).
// A staged in GROUP-tap chunks, double-buffered cp.async; syncs = 2 * (9/GROUP).
// FUSED: apply BN(stl)+ReLU of previous layer while staging B (interior only).
template<int KCI, int GROUP, bool FUSED>
__global__ __launch_bounds__(256, 2)
void k_conv(const __half* __restrict__ xb, const __half* __restrict__ apk,
            const float* __restrict__ bias, const float* __restrict__ ah,
            const float* __restrict__ aw, const float* __restrict__ stl,
            __half* __restrict__ yb, float* __restrict__ stats,
            int HO, int WO, int HpIn, int WpIn, int HpOut, int WpOut)
{
    constexpr int NT     = 144;                 // px per CTA
    constexpr int STRW   = 146;                 // strip width (px + 2 halo)
    constexpr int PITCH  = 2 * KCI + 16;        // bytes per smem row
    constexpr int PRH    = KCI + 8;             // halfs per packed-A row
    constexpr int ACH    = 128 * PITCH;         // per-tap A chunk
    constexpr int GCH    = GROUP * ACH;         // per-group A chunk
    constexpr int NG     = 9 / GROUP;           // staging groups
    constexpr int KSTEPS = KCI / 16;
    constexpr int BU4    = KCI / 8;             // uint4 per B px
    constexpr int SMB  = 0;
    constexpr int SMA  = 3 * STRW * PITCH;
    constexpr int SMCW = SMA + 2 * GCH;
    constexpr int SMBI = SMCW + 4 * NT * 4;
    constexpr int SMY  = SMBI + 128;
    constexpr int SMPP = SMY + NT * 32 * 2;

    extern __shared__ char smraw[];
    char* bsm = smraw + SMB;
    float* cws = (float*)(smraw + SMCW);        // [r4][144]
    float* bias_s = (float*)(smraw + SMBI);
    __half* ysm = (__half*)(smraw + SMY);       // [144 px][32 ch]
    float2* pp = (float2*)(smraw + SMPP);       // 8 warps x 32 ch
    const uint32_t SB = smem_u32(smraw);

    const int tid = threadIdx.x;
    const int lane = tid & 31;
    const int wid = tid >> 5;                   // 0..7
    const int h  = blockIdx.y;
    const int w0 = blockIdx.x * NT;
    const int b  = blockIdx.z >> 1;
    const int mh = blockIdx.z & 1;
    const int npx = min(NT, WO - w0);

    // prefetch A groups 0,1 (cp.async, double buffer)
    {
        constexpr int NU = GCH / 16;
#pragma unroll
        for (int t = 0; t < 2; ++t) {
            const char* src = (const char*)(apk + (size_t)(mh * 9 + t * GROUP) * 128 * PRH);
            uint32_t dst = SB + SMA + t * GCH;
            for (int i = tid; i < NU; i += 256) cpa16(dst + i * 16, src + i * 16);
            CP_COMMIT();
        }
    }

    // stage B: 3 input-row strips x 146 px (BN+ReLU fused if FUSED, interior only)
    for (int i = tid; i < 3 * STRW * BU4; i += 256) {
        int q = i % BU4;
        int p = i / BU4;
        int strip = p / STRW, c = p - strip * STRW;
        int row = h + strip;
        int col = min(w0 + c, WpIn - 1);
        uint4 v = *((const uint4*)(xb + ((size_t)(b * HpIn + row) * WpIn + col) * 64) + q);
        if (FUSED) {
            if (row >= 2 && row < HpIn - 2 && col >= 2 && col < WpIn - 2) {
                __half* hv = (__half*)&v;
#pragma unroll
                for (int j = 0; j < 8; ++j) {
                    int ch = q * 8 + j;
                    float f = __half2float(hv[j]) * stl[ch] + stl[64 + ch];
                    hv[j] = __float2half(fmaxf(f, 0.f));
                }
            }
        }
        *(uint4*)(bsm + p * PITCH + q * 16) = v;
    }
    // combining weights (softmax over rank) per pixel
    if (tid < NT) {
        int w = min(w0 + tid, WO - 1);
        float lg[4], mx = -1e30f;
#pragma unroll
        for (int r = 0; r < 4; ++r) { lg[r] = ah[r * HO + h] + aw[r * WO + w]; mx = fmaxf(mx, lg[r]); }
        float es = 0.f;
#pragma unroll
        for (int r = 0; r < 4; ++r) { lg[r] = expf(lg[r] - mx); es += lg[r]; }
        float inv = 1.f / es;
#pragma unroll
        for (int r = 0; r < 4; ++r) cws[r * NT + tid] = lg[r] * inv;
    }
    if (tid < 32) bias_s[tid] = bias[mh * 32 + tid];

    float acc[2][9][4];
#pragma unroll
    for (int mi = 0; mi < 2; ++mi)
#pragma unroll
        for (int ni = 0; ni < 9; ++ni)
#pragma unroll
            for (int c = 0; c < 4; ++c) acc[mi][ni][c] = 0.f;

    const int moff = (wid >> 1) * 32;           // 4 m-warps
    const int noff = (wid & 1) * 72;            // 2 n-warps
    const int arow = lane & 15;
    const int acol16 = (lane >> 4) * 16;
    const int brow = (lane & 7) + ((lane >> 4) << 3);
    const int bcol16 = ((lane >> 3) & 1) * 16;
    const uint32_t a_base0 = SB + SMA + (moff + arow) * PITCH + acol16;

#pragma unroll 1
    for (int g = 0; g < NG; ++g) {
        if (g == NG - 1) { CP_WAIT0(); } else { CP_WAIT1(); }
        __syncthreads();
#pragma unroll
        for (int t = 0; t < GROUP; ++t) {
            const int kk = g * GROUP + t;
            const int kh = kk / 3, kw = kk - (kk / 3) * 3;
            const uint32_t a_base = a_base0 + (g & 1) * GCH + t * ACH;
            const uint32_t b_base = SB + (kh * STRW + noff + kw + brow) * PITCH + bcol16;
#pragma unroll
            for (int s = 0; s < KSTEPS; ++s) {
                uint32_t af[2][4];
                LDSM4(af[0], a_base + s * 32);
                LDSM4(af[1], a_base + 16 * PITCH + s * 32);
                uint32_t bf[4][4];
                uint32_t b8[2];
#pragma unroll
                for (int gq = 0; gq < 4; ++gq)
                    LDSM4(bf[gq], b_base + gq * (16 * PITCH) + s * 32);
                LDSM2(b8, b_base + 64 * PITCH + s * 32);
#pragma unroll
                for (int mi = 0; mi < 2; ++mi) {
#pragma unroll
                    for (int n8 = 0; n8 < 8; ++n8)
                        hmma(acc[mi][n8], af[mi], &bf[n8 >> 1][(n8 & 1) * 2]);
                    hmma(acc[mi][8], af[mi], b8);
                }
            }
        }
        __syncthreads();
        if (g + 2 < NG) {
            constexpr int NU = GCH / 16;
            const char* src = (const char*)(apk + (size_t)(mh * 9 + (g + 2) * GROUP) * 128 * PRH);
            uint32_t dst = SB + SMA + (g & 1) * GCH;
            for (int i = tid; i < NU; i += 256) cpa16(dst + i * 16, src + i * 16);
            CP_COMMIT();
        }
    }

    // ---- epilogue: rank combine (shfl over r), bias, fp16 to ysm ----
    const int r4 = (lane >> 2) & 3;
    const bool lead = (r4 == 0);
#pragma unroll
    for (int mi = 0; mi < 2; ++mi)
#pragma unroll
        for (int ni = 0; ni < 9; ++ni) {
            int px0 = noff + 8 * ni + 2 * (lane & 3);
            float v0 = acc[mi][ni][0] * cws[r4 * NT + px0];
            float v1 = acc[mi][ni][1] * cws[r4 * NT + px0 + 1];
            float v2 = acc[mi][ni][2] * cws[r4 * NT + px0];
            float v3 = acc[mi][ni][3] * cws[r4 * NT + px0 + 1];
            v0 += __shfl_xor_sync(~0u, v0, 4); v0 += __shfl_xor_sync(~0u, v0, 8);
            v1 += __shfl_xor_sync(~0u, v1, 4); v1 += __shfl_xor_sync(~0u, v1, 8);
            v2 += __shfl_xor_sync(~0u, v2, 4); v2 += __shfl_xor_sync(~0u, v2, 8);
            v3 += __shfl_xor_sync(~0u, v3, 4); v3 += __shfl_xor_sync(~0u, v3, 8);
            if (lead) {
                int o0 = (moff + 16 * mi + (lane >> 2)) >> 2;
                int o2 = o0 + 2;
                __half* yr = ysm + px0 * 32;
                yr[o0]      = __float2half(v0 + bias_s[o0]);
                yr[32 + o0] = __float2half(v1 + bias_s[o0]);
                yr[o2]      = __float2half(v2 + bias_s[o2]);
                yr[32 + o2] = __float2half(v3 + bias_s[o2]);
            }
        }
    __syncthreads();

    // BN stats (valid px only): 8 warp-blocks of 18 px
    {
        int ol = tid & 31, pb = tid >> 5;
        float s0 = 0.f, s1 = 0.f;
#pragma unroll
        for (int jj = 0; jj < 18; ++jj) {
            int j = pb * 18 + jj;
            if (j < npx) {
                float v = __half2float(ysm[j * 32 + ol]);
                s0 += v; s1 += v * v;
            }
        }
        pp[pb * 32 + ol] = make_float2(s0, s1);
    }
    __syncthreads();
    if (tid < 32) {
        float a0 = 0.f, a1 = 0.f;
#pragma unroll
        for (int pb2 = 0; pb2 < 8; ++pb2) {
            float2 u = pp[pb2 * 32 + tid];
            a0 += u.x; a1 += u.y;
        }
        atomicAdd(&stats[mh * 32 + tid], a0);
        atomicAdd(&stats[64 + mh * 32 + tid], a1);
    }
    // store NHWC fp16 (this CTA's 32-ch half), halo offset +2
    for (int i = tid; i < npx * 4; i += 256) {
        int p = i >> 2, q = i & 3;
        *(uint4*)(yb + ((size_t)(b * HpOut + h + 2) * WpOut + (w0 + p + 2)) * 64
                  + mh * 32 + q * 8) = *(const uint4*)(ysm + p * 32 + q * 8);
    }
}

extern "C" void kernel_launch(void* const* d_in, const int* in_sizes, int n_in,
                              void* d_out, int out_size) {
    const float* x   = (const float*)d_in[0];
    const float* w1  = (const float*)d_in[1];
    const float* b1  = (const float*)d_in[2];
    const float* a1h = (const float*)d_in[3];
    const float* a1w = (const float*)d_in[4];
    const float* g1  = (const float*)d_in[5];
    const float* be1 = (const float*)d_in[6];
    const float* w2  = (const float*)d_in[7];
    const float* b2  = (const float*)d_in[8];
    const float* a2h = (const float*)d_in[9];
    const float* a2w = (const float*)d_in[10];
    const float* g2  = (const float*)d_in[11];
    const float* be2 = (const float*)d_in[12];

    __half *xb1, *xb2, *y2, *ap1, *ap2;
    float *stats, *st;
    cudaGetSymbolAddress((void**)&xb1, g_xb1);
    cudaGetSymbolAddress((void**)&xb2, g_xb2);
    cudaGetSymbolAddress((void**)&y2, g_y2);
    cudaGetSymbolAddress((void**)&ap1, g_apk1);
    cudaGetSymbolAddress((void**)&ap2, g_apk2);
    cudaGetSymbolAddress((void**)&stats, g_stats);
    cudaGetSymbolAddress((void**)&st, g_st);

    // smem: B + 2*GROUP*A + cws + bias + ysm + pp
    const int SM1 = 3 * 146 * 80 + 2 * 3 * 128 * 80 + 2304 + 128 + 9216 + 2048;   // 110,176
    const int SM2 = 3 * 146 * 144 + 2 * 1 * 128 * 144 + 2304 + 128 + 9216 + 2048; // 113,632
    cudaFuncSetAttribute((const void*)k_conv<32, 3, false>,
                         cudaFuncAttributeMaxDynamicSharedMemorySize, SM1);
    cudaFuncSetAttribute((const void*)k_conv<64, 1, true>,
                         cudaFuncAttributeMaxDynamicSharedMemorySize, SM2);

    // Launch order: conv1 is launch #4 (ncu empirically profiles the 4th launch).
    k_tin<<<16 * 128, 256>>>((const float4*)x, xb1);                                   // 1
    k_zero_halo<<<(16 * (4 * 260 + 128 * 4) * 8 + 255) / 256, 256>>>(xb1, 132, 260);   // 2
    k_pack<<<(2 * 9 * 128 * 40 + 255) / 256, 256>>>(w1, ap1, 32, 40, stats);           // 3 (+stats zero)
    k_conv<32, 3, false><<<dim3(2, HO1, 32), 256, SM1>>>(xb1, ap1, b1, a1h, a1w,       // 4
                                                         nullptr, xb2, stats,
                                                         HO1, WO1, 132, 260, 134, 262);
    k_pack<<<(2 * 9 * 128 * 72 + 255) / 256, 256>>>(w2, ap2, 64, 72, nullptr);         // 5
    k_zero_halo<<<(16 * (4 * 262 + 130 * 4) * 8 + 255) / 256, 256>>>(xb2, 134, 262);   // 6
    k_finalize<<<1, 64>>>(stats, g1, be1, st, (float)TOT1);                            // 7
    k_conv<64, 1, true><<<dim3(2, HO2, 32), 256, SM2>>>(xb2, ap2, b2, a2h, a2w, st,    // 8
                                                        y2, stats + 128,
                                                        HO2, WO2, 134, 262, 136, 264);
    k_finalize<<<1, 64>>>(stats + 128, g2, be2, st + 128, (float)TOT2);                // 9
    k_pool<<<(16 * 44 * 86 * 8 + 255) / 256, 256>>>(y2, st + 128, (float*)d_out);      // 10
}